// round 13
// baseline (speedup 1.0000x reference)
#include <cuda_runtime.h>
#include <cuda_bf16.h>
#include <cstdint>

#define Bsz  512
#define Ssz  1024
#define Esz  48
#define Hsz  128
#define NCLS 2000
#define NB   8                 // batches per cluster (MMA n dim)
#define NKK  11                // K chunks of 16 (176 = 128 h + 48 e)
#define NFR  (32 * NKK)        // 352 A-fragments per cluster
#define FRW  44                // fragments per warp (11 k x 4 gates)
#define HFR  (NFR / 2)         // 176 fragments per CTA (its j-half)
#define SROW 90                // state row stride in u32 (88 used + pad)

// Fragment images (fragblk = W*44 + kk*4 + g, W = global j-tile = rank*4+w).
__device__ uint32_t g_whiFrag[NFR * 128];
__device__ uint32_t g_wloFrag[NFR * 128];
__device__ float    g_bias4[4 * Hsz];
__device__ float    g_wfcT[Hsz * NCLS];
__device__ float    g_hfin[Bsz * Hsz];

__device__ __forceinline__ float tanha(float x) {
    float y; asm("tanh.approx.f32 %0, %1;" : "=f"(y) : "f"(x)); return y;
}
__device__ __forceinline__ float siga(float x) { return fmaf(0.5f, tanha(0.5f * x), 0.5f); }

__device__ __forceinline__ void mma(float* d, uint4 a, uint32_t b0, uint32_t b1) {
    asm volatile("mma.sync.aligned.m16n8k16.row.col.f32.bf16.bf16.f32 "
        "{%0,%1,%2,%3}, {%4,%5,%6,%7}, {%8,%9}, {%0,%1,%2,%3};"
        : "+f"(d[0]), "+f"(d[1]), "+f"(d[2]), "+f"(d[3])
        : "r"(a.x), "r"(a.y), "r"(a.z), "r"(a.w), "r"(b0), "r"(b1));
}
__device__ __forceinline__ uint32_t smem_u32(const void* p) {
    uint32_t a;
    asm("{ .reg .u64 t; cvta.to.shared.u64 t, %1; cvt.u32.u64 %0, t; }" : "=r"(a) : "l"(p));
    return a;
}

// ---------------------------------------------------------------------------
// Prep (identical layout to R12).
// ---------------------------------------------------------------------------
__global__ void prep_kernel(const float* __restrict__ w_ih, const float* __restrict__ w_hh,
                            const float* __restrict__ b_ih, const float* __restrict__ b_hh,
                            const float* __restrict__ w_fc) {
    int i = blockIdx.x * blockDim.x + threadIdx.x;
    if (i < NFR * 128) {
        int fragblk = i >> 7, rem = i & 127;
        int lane = rem >> 2, ri = rem & 3;
        int w = fragblk / FRW, f = fragblk % FRW, kk = f >> 2, g = f & 3;
        int r  = (lane >> 2) + (ri & 1) * 8;
        int c0 = (lane & 3) * 2 + (ri >> 1) * 8;
        int R = g * 128 + w * 16 + r;
        int K = kk * 16 + c0;
        float v0 = (K     < 128) ? w_hh[R * Hsz + K]     : w_ih[R * Esz + K - 128];
        float v1 = (K + 1 < 128) ? w_hh[R * Hsz + K + 1] : w_ih[R * Esz + K + 1 - 128];
        __nv_bfloat16 h0 = __float2bfloat16(v0), h1 = __float2bfloat16(v1);
        __nv_bfloat16 l0 = __float2bfloat16(v0 - __bfloat162float(h0));
        __nv_bfloat16 l1 = __float2bfloat16(v1 - __bfloat162float(h1));
        g_whiFrag[i] = (uint32_t)__bfloat16_as_ushort(h0) | ((uint32_t)__bfloat16_as_ushort(h1) << 16);
        g_wloFrag[i] = (uint32_t)__bfloat16_as_ushort(l0) | ((uint32_t)__bfloat16_as_ushort(l1) << 16);
    }
    if (i < 4 * Hsz) g_bias4[i] = b_ih[i] + b_hh[i];
    if (i < Hsz * NCLS) {
        int k = i / NCLS, n = i % NCLS;
        g_wfcT[i] = w_fc[n * Hsz + k];
    }
}

// ---------------------------------------------------------------------------
// LSTM recurrence: cluster-2 j-split. CTA rank r: all gates, j in [64r,64r+64).
// Per step: HMMA -> in-register combine -> h hi/lo to own + peer next-state
// (st.shared::cluster) -> fence + remote mbarrier arrive -> acquire wait.
// ---------------------------------------------------------------------------
struct alignas(16) Smem {
    uint32_t whiA[HFR * 128];      // 88 KB: this CTA's fragment half
    uint32_t sHi[2][NB * SROW];    // state hi, double-buffered (full K)
    uint32_t sLo[2][NB * SROW];    // state lo
    uint64_t mbar;
};

__device__ __forceinline__ void st_u16_local(uint32_t* base, int idx, int hf, uint16_t v) {
    ((uint16_t*)&base[idx])[hf] = v;
}
__device__ __forceinline__ void st_u16_remote(uint32_t addr, uint16_t v) {
    asm volatile("st.shared::cluster.u16 [%0], %1;" :: "r"(addr), "h"(v) : "memory");
}

__global__ void __launch_bounds__(128, 1)
lstm_kernel(const int* __restrict__ x, const float* __restrict__ emb) {
    extern __shared__ char smraw[];
    Smem* s = (Smem*)smraw;
    const int tid = threadIdx.x;
    const int w   = tid >> 5, l = tid & 31;
    const int B0  = (blockIdx.x >> 1) * NB;
    uint32_t rank;
    asm("mov.u32 %0, %%cluster_ctarank;" : "=r"(rank));
    const uint32_t smb = smem_u32(smraw);
    uint32_t peerBase;
    asm("mapa.shared::cluster.u32 %0, %1, %2;" : "=r"(peerBase) : "r"(smb), "r"(rank ^ 1));
    const uint32_t mbarOff = (uint32_t)((char*)&s->mbar - smraw);

    // Stage this CTA's Whi fragment half; zero both state buffers.
    const uint4* gsrc = (const uint4*)(g_whiFrag + rank * (HFR * 128));
    for (int i = tid; i < HFR * 128 / 4; i += 128)
        ((uint4*)s->whiA)[i] = gsrc[i];
    for (int i = tid; i < 2 * NB * SROW; i += 128) {
        (&s->sHi[0][0])[i] = 0;
        (&s->sLo[0][0])[i] = 0;
    }
    if (tid == 0)
        asm volatile("mbarrier.init.shared.b64 [%0], 1;" :: "r"(smb + mbarOff) : "memory");

    // Wlo fragments for this warp (global j-tile W = rank*4 + w): 176 regs.
    uint4 wlo[FRW];
    #pragma unroll
    for (int f = 0; f < FRW; f++)
        wlo[f] = ((const uint4*)g_wloFrag)[(((rank * 4 + w) * FRW) + f) * 32 + l];

    __syncthreads();   // zeros + mbar init before e(0) writes / peer traffic

    // Embedding slots: 384 slots over 128 threads -> 3 each.
    int sb[3], se[3], tv[3];
    #pragma unroll
    for (int q = 0; q < 3; q++) {
        const int slot = tid + q * 128;
        sb[q] = slot / Esz; se[q] = slot % Esz;
        const int t0 = __ldg(&x[(B0 + sb[q]) * Ssz]);
        const float v = __ldg(&emb[t0 * Esz + se[q]]);
        __nv_bfloat16 hi = __float2bfloat16(v);
        __nv_bfloat16 lo = __float2bfloat16(v - __bfloat162float(hi));
        const int k = 128 + se[q], kp = k >> 1, hf = k & 1;
        st_u16_local(&s->sHi[0][sb[q] * SROW], kp, hf, __bfloat16_as_ushort(hi));
        st_u16_local(&s->sLo[0][sb[q] * SROW], kp, hf, __bfloat16_as_ushort(lo));
        tv[q] = __ldg(&x[(B0 + sb[q]) * Ssz + 1]);
    }

    // Cells: j0 = rank*64 + w*16 + (l>>2), j1 = j0+8 ; b = (l&3)*2 (+1).
    const int j0 = rank * 64 + w * 16 + (l >> 2);
    const int j1 = j0 + 8;
    const int bc = (l & 3) * 2;
    float bias_[4][2];
    #pragma unroll
    for (int g = 0; g < 4; g++) {
        bias_[g][0] = g_bias4[g * Hsz + j0];
        bias_[g][1] = g_bias4[g * Hsz + j1];
    }
    float cc[4] = {0, 0, 0, 0};

    const uint4* aP = (const uint4*)(s->whiA) + w * FRW * 32 + l;

    // Cluster barrier: both CTAs' mbarriers + state buffers initialized.
    asm volatile("barrier.cluster.arrive.aligned;" ::: "memory");
    asm volatile("barrier.cluster.wait.aligned;" ::: "memory");
    __syncthreads();

    for (int st = 0; st < Ssz; st++) {
        const int buf = st & 1, nbuf = buf ^ 1;
        const uint32_t* sh = s->sHi[buf] + (l >> 2) * SROW + (l & 3);
        const uint32_t* sl = s->sLo[buf] + (l >> 2) * SROW + (l & 3);

        // Prefetch next embeddings/tokens (fly under HMMA).
        const bool doE = (st + 1 < Ssz);
        float ev[3]; int tn[3];
        #pragma unroll
        for (int q = 0; q < 3; q++) {
            ev[q] = doE ? __ldg(&emb[tv[q] * Esz + se[q]]) : 0.0f;
            tn[q] = (st + 2 < Ssz) ? __ldg(&x[(B0 + sb[q]) * Ssz + st + 2]) : 0;
        }

        // Bias-seeded accumulators.
        float d[16];
        #pragma unroll
        for (int g = 0; g < 4; g++) {
            d[g * 4 + 0] = bias_[g][0]; d[g * 4 + 1] = bias_[g][0];
            d[g * 4 + 2] = bias_[g][1]; d[g * 4 + 3] = bias_[g][1];
        }

        // HMMA: 11 k-chunks x (3 terms x 4 gates).
        #pragma unroll
        for (int kk = 0; kk < NKK; kk++) {
            const uint32_t bhi0 = sh[kk * 8], bhi1 = sh[kk * 8 + 4];
            const uint32_t blo0 = sl[kk * 8], blo1 = sl[kk * 8 + 4];
            uint4 ahi[4];
            #pragma unroll
            for (int g = 0; g < 4; g++) ahi[g] = aP[(kk * 4 + g) * 32];
            #pragma unroll
            for (int g = 0; g < 4; g++) mma(&d[g * 4], ahi[g], bhi0, bhi1);
            #pragma unroll
            for (int g = 0; g < 4; g++) mma(&d[g * 4], ahi[g], blo0, blo1);
            #pragma unroll
            for (int g = 0; g < 4; g++) mma(&d[g * 4], wlo[kk * 4 + g], bhi0, bhi1);
        }

        // In-register combine: cells q = (row q>>1, batch bc + (q&1)).
        if (st == Ssz - 1) {
            #pragma unroll
            for (int q = 0; q < 4; q++) {
                const float iv = siga(d[0 + q]);
                const float fv = siga(d[4 + q]);
                const float gv = tanha(d[8 + q]);
                const float ov = siga(d[12 + q]);
                cc[q] = fv * cc[q] + iv * gv;
                const float hv = ov * tanha(cc[q]);
                g_hfin[(B0 + bc + (q & 1)) * Hsz + j0 + (q >> 1) * 8] = hv;
            }
        } else {
            uint32_t* nHi = s->sHi[nbuf];
            uint32_t* nLo = s->sLo[nbuf];
            #pragma unroll
            for (int q = 0; q < 4; q++) {
                const float iv = siga(d[0 + q]);
                const float fv = siga(d[4 + q]);
                const float gv = tanha(d[8 + q]);
                const float ov = siga(d[12 + q]);
                cc[q] = fv * cc[q] + iv * gv;
                const float hv = ov * tanha(cc[q]);
                const __nv_bfloat16 hi = __float2bfloat16(hv);
                const __nv_bfloat16 lo = __float2bfloat16(hv - __bfloat162float(hi));
                const int b = bc + (q & 1);
                const int k = j0 + (q >> 1) * 8, kp = k >> 1, hf = k & 1;
                const int idx = b * SROW + kp;
                st_u16_local(nHi, idx, hf, __bfloat16_as_ushort(hi));
                st_u16_local(nLo, idx, hf, __bfloat16_as_ushort(lo));
                const uint32_t offHi = (uint32_t)((char*)&nHi[idx] - smraw) + hf * 2;
                const uint32_t offLo = (uint32_t)((char*)&nLo[idx] - smraw) + hf * 2;
                st_u16_remote(peerBase + offHi, __bfloat16_as_ushort(hi));
                st_u16_remote(peerBase + offLo, __bfloat16_as_ushort(lo));
            }
            // Next embeddings (local only; peer loads its own copy).
            #pragma unroll
            for (int q = 0; q < 3; q++) {
                const __nv_bfloat16 hi = __float2bfloat16(ev[q]);
                const __nv_bfloat16 lo = __float2bfloat16(ev[q] - __bfloat162float(hi));
                const int k = 128 + se[q], kp = k >> 1, hf = k & 1;
                st_u16_local(&nHi[sb[q] * SROW], kp, hf, __bfloat16_as_ushort(hi));
                st_u16_local(&nLo[sb[q] * SROW], kp, hf, __bfloat16_as_ushort(lo));
            }
            __syncthreads();
            if (tid == 0) {
                asm volatile("fence.acq_rel.cluster;" ::: "memory");
                asm volatile("mbarrier.arrive.release.cluster.shared::cluster.b64 _, [%0];"
                             :: "r"(peerBase + mbarOff) : "memory");
            }
            {   // wait for peer's h-half (acquire, cluster scope)
                const uint32_t mb = smb + mbarOff;
                const uint32_t ph = (uint32_t)(st & 1);
                uint32_t done;
                asm volatile("{ .reg .pred p; mbarrier.try_wait.parity.acquire.cluster.shared::cta.b64 p, [%1], %2; selp.b32 %0, 1, 0, p; }"
                    : "=r"(done) : "r"(mb), "r"(ph) : "memory");
                if (!done) {
                    asm volatile("{ .reg .pred P1; WL_%=: mbarrier.try_wait.parity.acquire.cluster.shared::cta.b64 P1, [%0], %1, 0x989680; @P1 bra.uni WD_%=; bra.uni WL_%=; WD_%=: }"
                        :: "r"(mb), "r"(ph) : "memory");
                }
            }
        }
        #pragma unroll
        for (int q = 0; q < 3; q++) tv[q] = tn[q];
    }

    // No CTA exits while peer traffic could be in flight.
    asm volatile("barrier.cluster.arrive.aligned;" ::: "memory");
    asm volatile("barrier.cluster.wait.aligned;" ::: "memory");
}

// ---------------------------------------------------------------------------
// FC epilogue.
// ---------------------------------------------------------------------------
__global__ void fc_kernel(const float* __restrict__ b_fc, float* __restrict__ out) {
    __shared__ float hs[8][Hsz];
    const int tid = threadIdx.x;
    const int n   = blockIdx.x * 128 + tid;
    const int bb  = blockIdx.y * 8;
    for (int i = tid; i < 8 * Hsz; i += 128)
        hs[i >> 7][i & 127] = g_hfin[(bb + (i >> 7)) * Hsz + (i & 127)];
    __syncthreads();
    if (n >= NCLS) return;
    const float bv = b_fc[n];
    float acc[8];
    #pragma unroll
    for (int i = 0; i < 8; i++) acc[i] = bv;
    #pragma unroll 4
    for (int k = 0; k < Hsz; k++) {
        const float w = g_wfcT[k * NCLS + n];
        #pragma unroll
        for (int i = 0; i < 8; i++) acc[i] = fmaf(hs[i][k], w, acc[i]);
    }
    #pragma unroll
    for (int i = 0; i < 8; i++) out[(bb + i) * NCLS + n] = acc[i];
}

extern "C" void kernel_launch(void* const* d_in, const int* in_sizes, int n_in,
                              void* d_out, int out_size) {
    const int*   x    = (const int*)  d_in[0];
    const float* emb  = (const float*)d_in[1];
    const float* w_ih = (const float*)d_in[2];
    const float* w_hh = (const float*)d_in[3];
    const float* b_ih = (const float*)d_in[4];
    const float* b_hh = (const float*)d_in[5];
    const float* w_fc = (const float*)d_in[6];
    const float* b_fc = (const float*)d_in[7];
    float* out = (float*)d_out;

    static bool attr_set = false;
    if (!attr_set) {
        cudaFuncSetAttribute(lstm_kernel, cudaFuncAttributeMaxDynamicSharedMemorySize,
                             (int)sizeof(Smem));
        attr_set = true;
    }

    prep_kernel<<<1000, 256>>>(w_ih, w_hh, b_ih, b_hh, w_fc);

    cudaLaunchConfig_t cfg = {};
    cfg.gridDim  = dim3(128, 1, 1);
    cfg.blockDim = dim3(128, 1, 1);
    cfg.dynamicSmemBytes = sizeof(Smem);
    cudaLaunchAttribute attrs[1];
    attrs[0].id = cudaLaunchAttributeClusterDimension;
    attrs[0].val.clusterDim.x = 2;
    attrs[0].val.clusterDim.y = 1;
    attrs[0].val.clusterDim.z = 1;
    cfg.attrs = attrs;
    cfg.numAttrs = 1;
    cudaLaunchKernelEx(&cfg, lstm_kernel, x, emb);

    fc_kernel<<<dim3((NCLS + 127) / 128, Bsz / 8), 128>>>(b_fc, out);
}

// round 14
// speedup vs baseline: 1.0626x; 1.0626x over previous
#include <cuda_runtime.h>
#include <cuda_bf16.h>
#include <cstdint>

#define Bsz  512
#define Ssz  1024
#define Esz  48
#define Hsz  128
#define NCLS 2000
#define NB   8                 // batches per cluster (MMA n dim)
#define NKK  11                // K chunks of 16 (176 = 128 h + 48 e)
#define NFR  (32 * NKK)        // 352 A-fragments per cluster
#define FRW  44                // fragments per warp (11 pos x 4 gates)
#define HFR  (NFR / 2)         // 176 fragments per CTA (its j-half)
#define SROW 90                // state row stride in u32 (88 used + pad)

// Fragment images. fragblk = W*44 + pos*4 + g, W = rank*4+w (global j-tile).
// Chunk permutation (baked in prep): pos 0..3 -> own-h chunks 4r..4r+3,
// pos 4..6 -> e chunks 8..10, pos 7..10 -> peer-h chunks 4(1-r)..4(1-r)+3.
__device__ uint32_t g_whiFrag[NFR * 128];
__device__ uint32_t g_wloFrag[NFR * 128];
__device__ float    g_bias4[4 * Hsz];
__device__ float    g_wfcT[Hsz * NCLS];
__device__ float    g_hfin[Bsz * Hsz];

__device__ __forceinline__ float tanha(float x) {
    float y; asm("tanh.approx.f32 %0, %1;" : "=f"(y) : "f"(x)); return y;
}
__device__ __forceinline__ float siga(float x) { return fmaf(0.5f, tanha(0.5f * x), 0.5f); }

__device__ __forceinline__ void mma(float* d, uint4 a, uint32_t b0, uint32_t b1) {
    asm volatile("mma.sync.aligned.m16n8k16.row.col.f32.bf16.bf16.f32 "
        "{%0,%1,%2,%3}, {%4,%5,%6,%7}, {%8,%9}, {%0,%1,%2,%3};"
        : "+f"(d[0]), "+f"(d[1]), "+f"(d[2]), "+f"(d[3])
        : "r"(a.x), "r"(a.y), "r"(a.z), "r"(a.w), "r"(b0), "r"(b1));
}
__device__ __forceinline__ uint32_t smem_u32(const void* p) {
    uint32_t a;
    asm("{ .reg .u64 t; cvta.to.shared.u64 t, %1; cvt.u32.u64 %0, t; }" : "=r"(a) : "l"(p));
    return a;
}

// ---------------------------------------------------------------------------
// Prep: per-rank permuted chunk order; otherwise identical to R12/R13 layout.
// ---------------------------------------------------------------------------
__global__ void prep_kernel(const float* __restrict__ w_ih, const float* __restrict__ w_hh,
                            const float* __restrict__ b_ih, const float* __restrict__ b_hh,
                            const float* __restrict__ w_fc) {
    int i = blockIdx.x * blockDim.x + threadIdx.x;
    if (i < NFR * 128) {
        int fragblk = i >> 7, rem = i & 127;
        int lane = rem >> 2, ri = rem & 3;
        int w = fragblk / FRW, f = fragblk % FRW, pos = f >> 2, g = f & 3;
        int rk = w >> 2;   // cluster rank this tile belongs to
        int kk = (pos < 4) ? (4 * rk + pos)
                           : ((pos < 7) ? (pos + 4) : (4 * (1 - rk) + pos - 7));
        int r  = (lane >> 2) + (ri & 1) * 8;
        int c0 = (lane & 3) * 2 + (ri >> 1) * 8;
        int R = g * 128 + w * 16 + r;
        int K = kk * 16 + c0;
        float v0 = (K     < 128) ? w_hh[R * Hsz + K]     : w_ih[R * Esz + K - 128];
        float v1 = (K + 1 < 128) ? w_hh[R * Hsz + K + 1] : w_ih[R * Esz + K + 1 - 128];
        __nv_bfloat16 h0 = __float2bfloat16(v0), h1 = __float2bfloat16(v1);
        __nv_bfloat16 l0 = __float2bfloat16(v0 - __bfloat162float(h0));
        __nv_bfloat16 l1 = __float2bfloat16(v1 - __bfloat162float(h1));
        g_whiFrag[i] = (uint32_t)__bfloat16_as_ushort(h0) | ((uint32_t)__bfloat16_as_ushort(h1) << 16);
        g_wloFrag[i] = (uint32_t)__bfloat16_as_ushort(l0) | ((uint32_t)__bfloat16_as_ushort(l1) << 16);
    }
    if (i < 4 * Hsz) g_bias4[i] = b_ih[i] + b_hh[i];
    if (i < Hsz * NCLS) {
        int k = i / NCLS, n = i % NCLS;
        g_wfcT[i] = w_fc[n * Hsz + k];
    }
}

// ---------------------------------------------------------------------------
// LSTM recurrence: cluster-2 j-split with pipelined exchange.
// Per step: sync -> local-chunk MMAs -> peer-wait -> peer-chunk MMAs ->
// combine -> local+remote state writes -> per-thread release-arrive.
// ---------------------------------------------------------------------------
struct alignas(16) Smem {
    uint32_t whiA[HFR * 128];      // 88 KB: this CTA's fragment half
    uint32_t sHi[2][NB * SROW];    // state hi, double-buffered (full K)
    uint32_t sLo[2][NB * SROW];    // state lo
    uint64_t mbar[2];              // ping-pong cluster barriers
};

__device__ __forceinline__ void st_u16_local(uint32_t* base, int idx, int hf, uint16_t v) {
    ((uint16_t*)&base[idx])[hf] = v;
}
__device__ __forceinline__ void st_u16_remote(uint32_t addr, uint16_t v) {
    asm volatile("st.shared::cluster.u16 [%0], %1;" :: "r"(addr), "h"(v) : "memory");
}

__global__ void __launch_bounds__(128, 1)
lstm_kernel(const int* __restrict__ x, const float* __restrict__ emb) {
    extern __shared__ char smraw[];
    Smem* s = (Smem*)smraw;
    const int tid = threadIdx.x;
    const int w   = tid >> 5, l = tid & 31;
    const int B0  = (blockIdx.x >> 1) * NB;
    uint32_t rank;
    asm("mov.u32 %0, %%cluster_ctarank;" : "=r"(rank));
    const uint32_t smb = smem_u32(smraw);
    uint32_t peerBase;
    asm("mapa.shared::cluster.u32 %0, %1, %2;" : "=r"(peerBase) : "r"(smb), "r"(rank ^ 1));
    const uint32_t mbOff0 = (uint32_t)((char*)&s->mbar[0] - smraw);
    const uint32_t mbOff1 = (uint32_t)((char*)&s->mbar[1] - smraw);

    // Stage this CTA's Whi fragment half; zero both state buffers.
    const uint4* gsrc = (const uint4*)(g_whiFrag + rank * (HFR * 128));
    for (int i = tid; i < HFR * 128 / 4; i += 128)
        ((uint4*)s->whiA)[i] = gsrc[i];
    for (int i = tid; i < 2 * NB * SROW; i += 128) {
        (&s->sHi[0][0])[i] = 0;
        (&s->sLo[0][0])[i] = 0;
    }
    if (tid == 0) {
        asm volatile("mbarrier.init.shared.b64 [%0], 128;" :: "r"(smb + mbOff0) : "memory");
        asm volatile("mbarrier.init.shared.b64 [%0], 128;" :: "r"(smb + mbOff1) : "memory");
    }

    // Wlo fragments for this warp (global tile W = rank*4 + w): 176 regs.
    uint4 wlo[FRW];
    #pragma unroll
    for (int f = 0; f < FRW; f++)
        wlo[f] = ((const uint4*)g_wloFrag)[(((rank * 4 + w) * FRW) + f) * 32 + l];

    __syncthreads();

    // Embedding slots: 384 slots over 128 threads -> 3 each.
    int sb[3], se[3], tv[3];
    #pragma unroll
    for (int q = 0; q < 3; q++) {
        const int slot = tid + q * 128;
        sb[q] = slot / Esz; se[q] = slot % Esz;
        const int t0 = __ldg(&x[(B0 + sb[q]) * Ssz]);
        const float v = __ldg(&emb[t0 * Esz + se[q]]);
        __nv_bfloat16 hi = __float2bfloat16(v);
        __nv_bfloat16 lo = __float2bfloat16(v - __bfloat162float(hi));
        const int k = 128 + se[q], kp = k >> 1, hf = k & 1;
        st_u16_local(&s->sHi[0][sb[q] * SROW], kp, hf, __bfloat16_as_ushort(hi));
        st_u16_local(&s->sLo[0][sb[q] * SROW], kp, hf, __bfloat16_as_ushort(lo));
        tv[q] = __ldg(&x[(B0 + sb[q]) * Ssz + 1]);
    }

    // Cells: j0 = rank*64 + w*16 + (l>>2), j1 = j0+8 ; b = (l&3)*2 (+1).
    const int j0 = rank * 64 + w * 16 + (l >> 2);
    const int j1 = j0 + 8;
    const int bc = (l & 3) * 2;
    float bias_[4][2];
    #pragma unroll
    for (int g = 0; g < 4; g++) {
        bias_[g][0] = g_bias4[g * Hsz + j0];
        bias_[g][1] = g_bias4[g * Hsz + j1];
    }
    float cc[4] = {0, 0, 0, 0};

    const uint4* aP = (const uint4*)(s->whiA) + w * FRW * 32 + l;
    const int ownC  = 4 * rank;          // own-h chunk base
    const int peerC = 4 * (rank ^ 1);    // peer-h chunk base

    // Both CTAs' mbarriers initialized before any arrivals.
    asm volatile("barrier.cluster.arrive.aligned;" ::: "memory");
    asm volatile("barrier.cluster.wait.aligned;" ::: "memory");
    // Pre-satisfy step-0 wait: every thread arrives on peer mbar[0].
    asm volatile("mbarrier.arrive.release.cluster.shared::cluster.b64 _, [%0];"
                 :: "r"(peerBase + mbOff0) : "memory");

    for (int st = 0; st < Ssz; st++) {
        const int buf = st & 1, nbuf = buf ^ 1;
        const uint32_t* sh = s->sHi[buf] + (l >> 2) * SROW + (l & 3);
        const uint32_t* sl = s->sLo[buf] + (l >> 2) * SROW + (l & 3);

        __syncthreads();   // previous step's LOCAL state writes visible

        // Prefetch next embeddings/tokens (fly under HMMA).
        const bool doE = (st + 1 < Ssz);
        float ev[3]; int tn[3];
        #pragma unroll
        for (int q = 0; q < 3; q++) {
            ev[q] = doE ? __ldg(&emb[tv[q] * Esz + se[q]]) : 0.0f;
            tn[q] = (st + 2 < Ssz) ? __ldg(&x[(B0 + sb[q]) * Ssz + st + 2]) : 0;
        }

        float d[16];
        #pragma unroll
        for (int g = 0; g < 4; g++) {
            d[g * 4 + 0] = bias_[g][0]; d[g * 4 + 1] = bias_[g][0];
            d[g * 4 + 2] = bias_[g][1]; d[g * 4 + 3] = bias_[g][1];
        }

        // --- LOCAL chunks: own-h (pos 0..3) + e (pos 4..6) ---
        #pragma unroll
        for (int pos = 0; pos < 7; pos++) {
            const int bchunk = (pos < 4) ? (ownC + pos) : (pos + 4);
            const uint32_t bhi0 = sh[bchunk * 8], bhi1 = sh[bchunk * 8 + 4];
            const uint32_t blo0 = sl[bchunk * 8], blo1 = sl[bchunk * 8 + 4];
            uint4 ahi[4];
            #pragma unroll
            for (int g = 0; g < 4; g++) ahi[g] = aP[(pos * 4 + g) * 32];
            #pragma unroll
            for (int g = 0; g < 4; g++) mma(&d[g * 4], ahi[g], bhi0, bhi1);
            #pragma unroll
            for (int g = 0; g < 4; g++) mma(&d[g * 4], ahi[g], blo0, blo1);
            #pragma unroll
            for (int g = 0; g < 4; g++) mma(&d[g * 4], wlo[pos * 4 + g], bhi0, bhi1);
        }

        // --- wait for peer's h-half (ping-pong barrier, acquire) ---
        {
            const uint32_t mb = smb + ((st & 1) ? mbOff1 : mbOff0);
            const uint32_t ph = (uint32_t)((st >> 1) & 1);
            uint32_t done;
            asm volatile("{ .reg .pred p; mbarrier.try_wait.parity.acquire.cluster.shared::cta.b64 p, [%1], %2; selp.b32 %0, 1, 0, p; }"
                : "=r"(done) : "r"(mb), "r"(ph) : "memory");
            if (!done) {
                asm volatile("{ .reg .pred P1; WL_%=: mbarrier.try_wait.parity.acquire.cluster.shared::cta.b64 P1, [%0], %1, 0x989680; @P1 bra.uni WD_%=; bra.uni WL_%=; WD_%=: }"
                    :: "r"(mb), "r"(ph) : "memory");
            }
        }

        // --- PEER chunks (pos 7..10) ---
        #pragma unroll
        for (int pos = 7; pos < 11; pos++) {
            const int bchunk = peerC + (pos - 7);
            const uint32_t bhi0 = sh[bchunk * 8], bhi1 = sh[bchunk * 8 + 4];
            const uint32_t blo0 = sl[bchunk * 8], blo1 = sl[bchunk * 8 + 4];
            uint4 ahi[4];
            #pragma unroll
            for (int g = 0; g < 4; g++) ahi[g] = aP[(pos * 4 + g) * 32];
            #pragma unroll
            for (int g = 0; g < 4; g++) mma(&d[g * 4], ahi[g], bhi0, bhi1);
            #pragma unroll
            for (int g = 0; g < 4; g++) mma(&d[g * 4], ahi[g], blo0, blo1);
            #pragma unroll
            for (int g = 0; g < 4; g++) mma(&d[g * 4], wlo[pos * 4 + g], bhi0, bhi1);
        }

        // --- combine ---
        if (st == Ssz - 1) {
            #pragma unroll
            for (int q = 0; q < 4; q++) {
                const float iv = siga(d[0 + q]);
                const float fv = siga(d[4 + q]);
                const float gv = tanha(d[8 + q]);
                const float ov = siga(d[12 + q]);
                cc[q] = fv * cc[q] + iv * gv;
                const float hv = ov * tanha(cc[q]);
                g_hfin[(B0 + bc + (q & 1)) * Hsz + j0 + (q >> 1) * 8] = hv;
            }
        } else {
            uint32_t* nHi = s->sHi[nbuf];
            uint32_t* nLo = s->sLo[nbuf];
            #pragma unroll
            for (int q = 0; q < 4; q++) {
                const float iv = siga(d[0 + q]);
                const float fv = siga(d[4 + q]);
                const float gv = tanha(d[8 + q]);
                const float ov = siga(d[12 + q]);
                cc[q] = fv * cc[q] + iv * gv;
                const float hv = ov * tanha(cc[q]);
                const __nv_bfloat16 hi = __float2bfloat16(hv);
                const __nv_bfloat16 lo = __float2bfloat16(hv - __bfloat162float(hi));
                const int b = bc + (q & 1);
                const int k = j0 + (q >> 1) * 8, kp = k >> 1, hf = k & 1;
                const int idx = b * SROW + kp;
                st_u16_local(nHi, idx, hf, __bfloat16_as_ushort(hi));
                st_u16_local(nLo, idx, hf, __bfloat16_as_ushort(lo));
                const uint32_t offHi = (uint32_t)((char*)&nHi[idx] - smraw) + hf * 2;
                const uint32_t offLo = (uint32_t)((char*)&nLo[idx] - smraw) + hf * 2;
                st_u16_remote(peerBase + offHi, __bfloat16_as_ushort(hi));
                st_u16_remote(peerBase + offLo, __bfloat16_as_ushort(lo));
            }
            #pragma unroll
            for (int q = 0; q < 3; q++) {
                const __nv_bfloat16 hi = __float2bfloat16(ev[q]);
                const __nv_bfloat16 lo = __float2bfloat16(ev[q] - __bfloat162float(hi));
                const int k = 128 + se[q], kp = k >> 1, hf = k & 1;
                st_u16_local(&nHi[sb[q] * SROW], kp, hf, __bfloat16_as_ushort(hi));
                st_u16_local(&nLo[sb[q] * SROW], kp, hf, __bfloat16_as_ushort(lo));
            }
            // Per-thread release-arrive on peer's NEXT-step barrier.
            const uint32_t pmb = peerBase + (((st + 1) & 1) ? mbOff1 : mbOff0);
            asm volatile("mbarrier.arrive.release.cluster.shared::cluster.b64 _, [%0];"
                         :: "r"(pmb) : "memory");
        }
        #pragma unroll
        for (int q = 0; q < 3; q++) tv[q] = tn[q];
    }

    // No CTA exits while peer traffic could be in flight.
    asm volatile("barrier.cluster.arrive.aligned;" ::: "memory");
    asm volatile("barrier.cluster.wait.aligned;" ::: "memory");
}

// ---------------------------------------------------------------------------
// FC epilogue.
// ---------------------------------------------------------------------------
__global__ void fc_kernel(const float* __restrict__ b_fc, float* __restrict__ out) {
    __shared__ float hs[8][Hsz];
    const int tid = threadIdx.x;
    const int n   = blockIdx.x * 128 + tid;
    const int bb  = blockIdx.y * 8;
    for (int i = tid; i < 8 * Hsz; i += 128)
        hs[i >> 7][i & 127] = g_hfin[(bb + (i >> 7)) * Hsz + (i & 127)];
    __syncthreads();
    if (n >= NCLS) return;
    const float bv = b_fc[n];
    float acc[8];
    #pragma unroll
    for (int i = 0; i < 8; i++) acc[i] = bv;
    #pragma unroll 4
    for (int k = 0; k < Hsz; k++) {
        const float w = g_wfcT[k * NCLS + n];
        #pragma unroll
        for (int i = 0; i < 8; i++) acc[i] = fmaf(hs[i][k], w, acc[i]);
    }
    #pragma unroll
    for (int i = 0; i < 8; i++) out[(bb + i) * NCLS + n] = acc[i];
}

extern "C" void kernel_launch(void* const* d_in, const int* in_sizes, int n_in,
                              void* d_out, int out_size) {
    const int*   x    = (const int*)  d_in[0];
    const float* emb  = (const float*)d_in[1];
    const float* w_ih = (const float*)d_in[2];
    const float* w_hh = (const float*)d_in[3];
    const float* b_ih = (const float*)d_in[4];
    const float* b_hh = (const float*)d_in[5];
    const float* w_fc = (const float*)d_in[6];
    const float* b_fc = (const float*)d_in[7];
    float* out = (float*)d_out;

    static bool attr_set = false;
    if (!attr_set) {
        cudaFuncSetAttribute(lstm_kernel, cudaFuncAttributeMaxDynamicSharedMemorySize,
                             (int)sizeof(Smem));
        attr_set = true;
    }

    prep_kernel<<<1000, 256>>>(w_ih, w_hh, b_ih, b_hh, w_fc);

    cudaLaunchConfig_t cfg = {};
    cfg.gridDim  = dim3(128, 1, 1);
    cfg.blockDim = dim3(128, 1, 1);
    cfg.dynamicSmemBytes = sizeof(Smem);
    cudaLaunchAttribute attrs[1];
    attrs[0].id = cudaLaunchAttributeClusterDimension;
    attrs[0].val.clusterDim.x = 2;
    attrs[0].val.clusterDim.y = 1;
    attrs[0].val.clusterDim.z = 1;
    cfg.attrs = attrs;
    cfg.numAttrs = 1;
    cudaLaunchKernelEx(&cfg, lstm_kernel, x, emb);

    fc_kernel<<<dim3((NCLS + 127) / 128, Bsz / 8), 128>>>(b_fc, out);
}

// round 15
// speedup vs baseline: 1.1052x; 1.0401x over previous
#include <cuda_runtime.h>
#include <cuda_bf16.h>
#include <cstdint>

#define Bsz  512
#define Ssz  1024
#define Esz  48
#define Hsz  128
#define NCLS 2000
#define NB   8                 // batches per CTA (MMA n dim)
#define NCTA (Bsz / NB)        // 64
#define NKK  11                // K chunks of 16 (176 = 128 h + 48 e)
#define NFR  (32 * NKK)        // 352 A-fragments per CTA
#define FRW  44                // fragments per warp (11 k x 4 gates)
#define SROW 100               // state row stride in u32 (88 used; ==4 mod 32
                               // -> 8 rows x 4-u32 windows tile all 32 banks)

// Prepared parameters (built by prep_kernel each launch).
// Fragment images: u32 index = fragblk*128 + lane*4 + ri,
//   fragblk = w*44 + kk*4 + g  ->  W rows g*128 + w*16 + r  (warp = j-slice)
__device__ uint32_t g_whiFrag[NFR * 128];
__device__ uint32_t g_wloFrag[NFR * 128];
__device__ float    g_bias4[4 * Hsz];
__device__ float    g_wfcT[Hsz * NCLS];
__device__ float    g_hfin[Bsz * Hsz];

__device__ __forceinline__ float tanha(float x) {
    float y; asm("tanh.approx.f32 %0, %1;" : "=f"(y) : "f"(x)); return y;
}
__device__ __forceinline__ float siga(float x) { return fmaf(0.5f, tanha(0.5f * x), 0.5f); }

// m16n8k16 bf16 MMA, fp32 accumulate (baseline PTX, sm_80+).
__device__ __forceinline__ void mma(float* d, uint4 a, uint32_t b0, uint32_t b1) {
    asm volatile("mma.sync.aligned.m16n8k16.row.col.f32.bf16.bf16.f32 "
        "{%0,%1,%2,%3}, {%4,%5,%6,%7}, {%8,%9}, {%0,%1,%2,%3};"
        : "+f"(d[0]), "+f"(d[1]), "+f"(d[2]), "+f"(d[3])
        : "r"(a.x), "r"(a.y), "r"(a.z), "r"(a.w), "r"(b0), "r"(b1));
}

// ---------------------------------------------------------------------------
// Prep. W[512,176]: rows gate-major (PyTorch i,f,g,o), K: 0..127 w_hh, 128..175 w_ih.
// A-frag (m16n8k16 row-A): lane l, reg ri: r=(l>>2)+(ri&1)*8, c0=(l&3)*2+(ri>>1)*8.
// Warp mapping: fragblk = w*44 + kk*4 + g  ->  R = g*128 + w*16 + r, K = kk*16+c.
// ---------------------------------------------------------------------------
__global__ void prep_kernel(const float* __restrict__ w_ih, const float* __restrict__ w_hh,
                            const float* __restrict__ b_ih, const float* __restrict__ b_hh,
                            const float* __restrict__ w_fc) {
    int i = blockIdx.x * blockDim.x + threadIdx.x;
    if (i < NFR * 128) {
        int fragblk = i >> 7, rem = i & 127;
        int lane = rem >> 2, ri = rem & 3;
        int w = fragblk / FRW, f = fragblk % FRW, kk = f >> 2, g = f & 3;
        int r  = (lane >> 2) + (ri & 1) * 8;
        int c0 = (lane & 3) * 2 + (ri >> 1) * 8;
        int R = g * 128 + w * 16 + r;
        int K = kk * 16 + c0;
        float v0 = (K     < 128) ? w_hh[R * Hsz + K]     : w_ih[R * Esz + K - 128];
        float v1 = (K + 1 < 128) ? w_hh[R * Hsz + K + 1] : w_ih[R * Esz + K + 1 - 128];
        __nv_bfloat16 h0 = __float2bfloat16(v0), h1 = __float2bfloat16(v1);
        __nv_bfloat16 l0 = __float2bfloat16(v0 - __bfloat162float(h0));
        __nv_bfloat16 l1 = __float2bfloat16(v1 - __bfloat162float(h1));
        g_whiFrag[i] = (uint32_t)__bfloat16_as_ushort(h0) | ((uint32_t)__bfloat16_as_ushort(h1) << 16);
        g_wloFrag[i] = (uint32_t)__bfloat16_as_ushort(l0) | ((uint32_t)__bfloat16_as_ushort(l1) << 16);
    }
    if (i < 4 * Hsz) g_bias4[i] = b_ih[i] + b_hh[i];
    if (i < Hsz * NCLS) {
        int k = i / NCLS, n = i % NCLS;
        g_wfcT[i] = w_fc[n * Hsz + k];
    }
}

// ---------------------------------------------------------------------------
// LSTM recurrence: fragment-aligned combine, double-buffered state,
// one barrier per step.  D = Whi*s_hi + Whi*s_lo + Wlo*s_hi  (fp32 acc).
// ---------------------------------------------------------------------------
struct alignas(16) Smem {
    uint32_t whiA[NFR * 128];      // 176 KB fragment image of Whi
    uint32_t sHi[2][NB * SROW];    // state hi, double-buffered
    uint32_t sLo[2][NB * SROW];    // state lo
};

__device__ __forceinline__ void write_state(uint32_t* hiB, uint32_t* loB,
                                            int b, int k, float v) {
    __nv_bfloat16 hi = __float2bfloat16(v);
    __nv_bfloat16 lo = __float2bfloat16(v - __bfloat162float(hi));
    const int kp = k >> 1, hf = k & 1;
    ((uint16_t*)&hiB[b * SROW + kp])[hf] = __bfloat16_as_ushort(hi);
    ((uint16_t*)&loB[b * SROW + kp])[hf] = __bfloat16_as_ushort(lo);
}

__global__ void __launch_bounds__(256, 1)
lstm_kernel(const int* __restrict__ x, const float* __restrict__ emb) {
    extern __shared__ char smraw[];
    Smem* s = (Smem*)smraw;
    const int tid = threadIdx.x;
    const int w   = tid >> 5, l = tid & 31;
    const int B0  = blockIdx.x * NB;

    // Stage Whi fragments; zero both state buffers.
    for (int i = tid; i < NFR * 128 / 4; i += 256)
        ((uint4*)s->whiA)[i] = ((const uint4*)g_whiFrag)[i];
    for (int i = tid; i < 2 * NB * SROW; i += 256) {
        (&s->sHi[0][0])[i] = 0;
        (&s->sLo[0][0])[i] = 0;
    }

    // Wlo fragments: stationary in registers (44 uint4 = 176 regs).
    uint4 wlo[FRW];
    #pragma unroll
    for (int f = 0; f < FRW; f++)
        wlo[f] = ((const uint4*)g_wloFrag)[(w * FRW + f) * 32 + l];

    // This lane's cells: j0/j1 = w*16 + (l>>2) [+8], b0/b1 = (l&3)*2 [+1].
    const int r0 = l >> 2;
    const int c0 = (l & 3) * 2;
    const int j0 = w * 16 + r0, j1 = j0 + 8;
    float bias_[4][2];
    #pragma unroll
    for (int g = 0; g < 4; g++) {
        bias_[g][0] = g_bias4[g * Hsz + j0];
        bias_[g][1] = g_bias4[g * Hsz + j1];
    }
    float cc[4] = {0, 0, 0, 0};   // cells q: (row r0,b0)(r0,b1)(r1,b0)(r1,b1)

    // Embedding slots: slot -> (b = slot/48, e = slot%48); 384 slots / 256 thr.
    const int  sb0 = tid / Esz, se0 = tid % Esz;
    const bool has1 = (tid < 128);
    const int  sb1 = (tid + 256) / Esz, se1 = (tid + 256) % Esz;
    int tv0 = 0, tv1 = 0;
    __syncthreads();     // zeros visible before e(0) writes
    {
        const int t0 = __ldg(&x[(B0 + sb0) * Ssz]);
        write_state(s->sHi[0], s->sLo[0], sb0, 128 + se0, __ldg(&emb[t0 * Esz + se0]));
        tv0 = __ldg(&x[(B0 + sb0) * Ssz + 1]);
        if (has1) {
            const int t1 = __ldg(&x[(B0 + sb1) * Ssz]);
            write_state(s->sHi[0], s->sLo[0], sb1, 128 + se1, __ldg(&emb[t1 * Esz + se1]));
            tv1 = __ldg(&x[(B0 + sb1) * Ssz + 1]);
        }
    }
    const uint4* aP = (const uint4*)(s->whiA) + w * FRW * 32 + l;
    __syncthreads();

    for (int st = 0; st < Ssz; st++) {
        const int buf = st & 1, nbuf = buf ^ 1;
        const uint32_t* sh = s->sHi[buf] + (l >> 2) * SROW + (l & 3);
        const uint32_t* sl = s->sLo[buf] + (l >> 2) * SROW + (l & 3);
        uint32_t* nHi = s->sHi[nbuf];
        uint32_t* nLo = s->sLo[nbuf];

        // Prefetch next embeddings/tokens (fly under HMMA).
        const bool doE = (st + 1 < Ssz);
        float ev0 = 0.0f, ev1 = 0.0f; int tn0 = 0, tn1 = 0;
        if (doE) {
            ev0 = __ldg(&emb[tv0 * Esz + se0]);
            if (has1) ev1 = __ldg(&emb[tv1 * Esz + se1]);
        }
        if (st + 2 < Ssz) {
            tn0 = __ldg(&x[(B0 + sb0) * Ssz + st + 2]);
            if (has1) tn1 = __ldg(&x[(B0 + sb1) * Ssz + st + 2]);
        }

        // Accumulators pre-seeded with bias (per gate / per row).
        float d[16];
        #pragma unroll
        for (int g = 0; g < 4; g++) {
            d[g * 4 + 0] = bias_[g][0]; d[g * 4 + 1] = bias_[g][0];
            d[g * 4 + 2] = bias_[g][1]; d[g * 4 + 3] = bias_[g][1];
        }

        // --- HMMA: 11 k-chunks x (3 terms x 4 gates), term-major interleave ---
        #pragma unroll
        for (int kk = 0; kk < NKK; kk++) {
            const uint32_t bhi0 = sh[kk * 8], bhi1 = sh[kk * 8 + 4];
            const uint32_t blo0 = sl[kk * 8], blo1 = sl[kk * 8 + 4];
            uint4 ahi[4];
            #pragma unroll
            for (int g = 0; g < 4; g++) ahi[g] = aP[(kk * 4 + g) * 32];
            #pragma unroll
            for (int g = 0; g < 4; g++) mma(&d[g * 4], ahi[g], bhi0, bhi1);
            #pragma unroll
            for (int g = 0; g < 4; g++) mma(&d[g * 4], ahi[g], blo0, blo1);
            #pragma unroll
            for (int g = 0; g < 4; g++) mma(&d[g * 4], wlo[kk * 4 + g], bhi0, bhi1);
        }

        // --- in-register combine: 4 cells, gates i/f/g/o = d[0/4/8/12 + q] ---
        #pragma unroll
        for (int q = 0; q < 4; q++) {
            const float iv = siga(d[0 + q]);
            const float fv = siga(d[4 + q]);
            const float gv = tanha(d[8 + q]);
            const float ov = siga(d[12 + q]);
            cc[q] = fv * cc[q] + iv * gv;
            const float hv = ov * tanha(cc[q]);
            write_state(nHi, nLo, c0 + (q & 1), j0 + (q >> 1) * 8, hv);
        }
        if (doE) {
            write_state(nHi, nLo, sb0, 128 + se0, ev0);
            if (has1) write_state(nHi, nLo, sb1, 128 + se1, ev1);
        }
        tv0 = tn0; tv1 = tn1;
        __syncthreads();
    }

    // Export final hidden state from state buffer (hi+lo reconstruction).
    const uint32_t* fHi = s->sHi[Ssz & 1];
    const uint32_t* fLo = s->sLo[Ssz & 1];
    for (int i = tid; i < NB * Hsz; i += 256) {
        const int b = i >> 7, jj = i & 127;
        const int kp = jj >> 1, hf = jj & 1;
        const float hi = __bfloat162float(__ushort_as_bfloat16(((const uint16_t*)&fHi[b * SROW + kp])[hf]));
        const float lo = __bfloat162float(__ushort_as_bfloat16(((const uint16_t*)&fLo[b * SROW + kp])[hf]));
        g_hfin[(B0 + b) * Hsz + jj] = hi + lo;
    }
}

// ---------------------------------------------------------------------------
// FC epilogue: out[b][n] = h_fin[b] . w_fc[n] + b_fc[n]
// ---------------------------------------------------------------------------
__global__ void fc_kernel(const float* __restrict__ b_fc, float* __restrict__ out) {
    __shared__ float hs[8][Hsz];
    const int tid = threadIdx.x;
    const int n   = blockIdx.x * 128 + tid;
    const int bb  = blockIdx.y * 8;
    for (int i = tid; i < 8 * Hsz; i += 128)
        hs[i >> 7][i & 127] = g_hfin[(bb + (i >> 7)) * Hsz + (i & 127)];
    __syncthreads();
    if (n >= NCLS) return;
    const float bv = b_fc[n];
    float acc[8];
    #pragma unroll
    for (int i = 0; i < 8; i++) acc[i] = bv;
    #pragma unroll 4
    for (int k = 0; k < Hsz; k++) {
        const float w = g_wfcT[k * NCLS + n];
        #pragma unroll
        for (int i = 0; i < 8; i++) acc[i] = fmaf(hs[i][k], w, acc[i]);
    }
    #pragma unroll
    for (int i = 0; i < 8; i++) out[(bb + i) * NCLS + n] = acc[i];
}

extern "C" void kernel_launch(void* const* d_in, const int* in_sizes, int n_in,
                              void* d_out, int out_size) {
    const int*   x    = (const int*)  d_in[0];
    const float* emb  = (const float*)d_in[1];
    const float* w_ih = (const float*)d_in[2];
    const float* w_hh = (const float*)d_in[3];
    const float* b_ih = (const float*)d_in[4];
    const float* b_hh = (const float*)d_in[5];
    const float* w_fc = (const float*)d_in[6];
    const float* b_fc = (const float*)d_in[7];
    float* out = (float*)d_out;

    static bool attr_set = false;
    if (!attr_set) {
        cudaFuncSetAttribute(lstm_kernel, cudaFuncAttributeMaxDynamicSharedMemorySize,
                             (int)sizeof(Smem));
        attr_set = true;
    }

    prep_kernel<<<1000, 256>>>(w_ih, w_hh, b_ih, b_hh, w_fc);
    lstm_kernel<<<NCTA, 256, sizeof(Smem)>>>(x, emb);
    fc_kernel<<<dim3((NCLS + 127) / 128, Bsz / 8), 128>>>(b_fc, out);
}